// round 1
// baseline (speedup 1.0000x reference)
#include <cuda_runtime.h>

#define BB 32
#define DD 512
#define KK 64
#define NNN 1024

#define NT1 128   // K1 n-tile
#define DT  16    // K1 d-chunk
#define NT2 32    // K2 n-chunk

// Scratch (allocation-free rule: __device__ globals)
__device__ __align__(16) float g_assign[(size_t)BB * KK * NNN]; // 8 MB
__device__ __align__(16) float g_vlad[(size_t)BB * DD * KK];    // 4 MB

typedef unsigned long long u64;

__device__ __forceinline__ void fma2(u64 &d, u64 a, u64 b, u64 c) {
    asm("fma.rn.f32x2 %0, %1, %2, %3;" : "=l"(d) : "l"(a), "l"(b), "l"(c));
}
__device__ __forceinline__ float2 unpack2(u64 v) {
    float2 r;
    asm("mov.b64 {%0, %1}, %2;" : "=f"(r.x), "=f"(r.y) : "l"(v));
    return r;
}

// ---------------------------------------------------------------------------
// K1: scores = W @ x  (64 x 128 tile per block), fused softmax over K,
//     writes assign[b,k,n].
// ---------------------------------------------------------------------------
__global__ void __launch_bounds__(256, 2)
k1_scores_softmax(const float* __restrict__ x, const float* __restrict__ w) {
    // 32 KB buffer: GEMM stage uses Wdup(8KB)+Xs(8KB); softmax reuses it as Ss(32KB)
    __shared__ __align__(16) char smraw[KK * NT1 * 4];
    float2 (*Wdup)[KK] = reinterpret_cast<float2(*)[KK]>(smraw);
    float  (*Xs)[NT1]  = reinterpret_cast<float(*)[NT1]>(smraw + DT * KK * sizeof(float2));
    float  (*Ss)[NT1]  = reinterpret_cast<float(*)[NT1]>(smraw);

    const int b   = blockIdx.y;
    const int n0  = blockIdx.x * NT1;
    const int tid = threadIdx.x;
    const int txn = tid & 31;   // n group: n = 4*txn + {0..3}
    const int tyk = tid >> 5;   // k group: k = tyk + 8*i

    const float* xb = x + (size_t)b * DD * NNN;

    u64 acc[8][2];
#pragma unroll
    for (int i = 0; i < 8; i++) { acc[i][0] = 0ull; acc[i][1] = 0ull; }

    const int kk   = tid >> 2;         // 0..63 (W load)
    const int dd4  = (tid & 3) << 2;   // 0,4,8,12
    const int xrow = tid >> 5;         // 0..7  (X load)
    const int xcol = (tid & 31) << 2;  // 0..124

    for (int dt = 0; dt < DD; dt += DT) {
        // W chunk, duplicated pairs for packed-FMA broadcast
        float4 wv = *reinterpret_cast<const float4*>(w + (size_t)kk * DD + dt + dd4);
        Wdup[dd4 + 0][kk] = make_float2(wv.x, wv.x);
        Wdup[dd4 + 1][kk] = make_float2(wv.y, wv.y);
        Wdup[dd4 + 2][kk] = make_float2(wv.z, wv.z);
        Wdup[dd4 + 3][kk] = make_float2(wv.w, wv.w);
        // X chunk
#pragma unroll
        for (int q = 0; q < 2; q++) {
            int dd = xrow + q * 8;
            *reinterpret_cast<float4*>(&Xs[dd][xcol]) =
                *reinterpret_cast<const float4*>(xb + (size_t)(dt + dd) * NNN + n0 + xcol);
        }
        __syncthreads();
#pragma unroll
        for (int dd = 0; dd < DT; dd++) {
            u64 xp0 = *reinterpret_cast<const u64*>(&Xs[dd][4 * txn]);
            u64 xp1 = *reinterpret_cast<const u64*>(&Xs[dd][4 * txn + 2]);
#pragma unroll
            for (int i = 0; i < 8; i++) {
                u64 wp = *reinterpret_cast<const u64*>(&Wdup[dd][tyk + 8 * i]);
                fma2(acc[i][0], wp, xp0, acc[i][0]);
                fma2(acc[i][1], wp, xp1, acc[i][1]);
            }
        }
        __syncthreads();
    }

    // scores -> Ss (overwrites GEMM staging; safe after the sync above)
#pragma unroll
    for (int i = 0; i < 8; i++) {
        float2 a0 = unpack2(acc[i][0]);
        float2 a1 = unpack2(acc[i][1]);
        float4 v = make_float4(a0.x, a0.y, a1.x, a1.y);
        *reinterpret_cast<float4*>(&Ss[tyk + 8 * i][4 * txn]) = v;
    }
    __syncthreads();

    // softmax over K per column; one thread per column
    if (tid < NT1) {
        const int c = tid;
        float mx = -1e30f;
#pragma unroll
        for (int k = 0; k < KK; k++) mx = fmaxf(mx, Ss[k][c]);
        float s = 0.f;
#pragma unroll
        for (int k = 0; k < KK; k++) {
            float e = __expf(Ss[k][c] - mx);
            Ss[k][c] = e;
            s += e;
        }
        float is = 1.f / s;
        float* ab = g_assign + ((size_t)b * KK) * NNN + n0 + c;
#pragma unroll
        for (int k = 0; k < KK; k++) ab[(size_t)k * NNN] = Ss[k][c] * is;
    }
}

// ---------------------------------------------------------------------------
// K2: vlad[b, d0:d0+128, :] = x[b] @ assign[b]^T  -  centers * asum
//     (asum computed redundantly per block; fused epilogue)
// ---------------------------------------------------------------------------
__global__ void __launch_bounds__(256, 2)
k2_vlad(const float* __restrict__ x, const float* __restrict__ centers) {
    __shared__ float2 Xd[NT2][128];   // duplicated x pairs, 32 KB
    __shared__ float  As[NT2][KK];    // assign chunk, 8 KB
    __shared__ float  asums[KK];

    const int b   = blockIdx.y;
    const int d0  = blockIdx.x * 128;
    const int tid = threadIdx.x;
    const int tx  = tid & 15;   // k: 4*tx + {0..3}
    const int tyy = tid >> 4;   // d: tyy + 16*i

    const float* xb = x + (size_t)b * DD * NNN;
    const float* ab = g_assign + (size_t)b * KK * NNN;

    u64 acc[8][2];
#pragma unroll
    for (int i = 0; i < 8; i++) { acc[i][0] = 0ull; acc[i][1] = 0ull; }
    float asum = 0.f;

    const int xd  = tid >> 1;          // 0..127
    const int xnb = (tid & 1) * 16;    // 0 or 16
    const int ak  = tid & 63;          // 0..63
    const int anb = (tid >> 6) * 8;    // 0,8,16,24

    for (int n0 = 0; n0 < NNN; n0 += NT2) {
#pragma unroll
        for (int q = 0; q < 4; q++) {
            float4 v = *reinterpret_cast<const float4*>(
                xb + (size_t)(d0 + xd) * NNN + n0 + xnb + 4 * q);
            Xd[xnb + 4 * q + 0][xd] = make_float2(v.x, v.x);
            Xd[xnb + 4 * q + 1][xd] = make_float2(v.y, v.y);
            Xd[xnb + 4 * q + 2][xd] = make_float2(v.z, v.z);
            Xd[xnb + 4 * q + 3][xd] = make_float2(v.w, v.w);
        }
#pragma unroll
        for (int q = 0; q < 2; q++) {
            float4 v = *reinterpret_cast<const float4*>(
                ab + (size_t)ak * NNN + n0 + anb + 4 * q);
            As[anb + 4 * q + 0][ak] = v.x;
            As[anb + 4 * q + 1][ak] = v.y;
            As[anb + 4 * q + 2][ak] = v.z;
            As[anb + 4 * q + 3][ak] = v.w;
        }
        __syncthreads();

        if (tid < KK) {
            float s = 0.f;
#pragma unroll
            for (int nn = 0; nn < NT2; nn++) s += As[nn][tid];
            asum += s;
        }

#pragma unroll 4
        for (int nn = 0; nn < NT2; nn++) {
            u64 ap0 = *reinterpret_cast<const u64*>(&As[nn][4 * tx]);
            u64 ap1 = *reinterpret_cast<const u64*>(&As[nn][4 * tx + 2]);
#pragma unroll
            for (int i = 0; i < 8; i++) {
                u64 xp = *reinterpret_cast<const u64*>(&Xd[nn][tyy + 16 * i]);
                fma2(acc[i][0], xp, ap0, acc[i][0]);
                fma2(acc[i][1], xp, ap1, acc[i][1]);
            }
        }
        __syncthreads();
    }

    if (tid < KK) asums[tid] = asum;
    __syncthreads();

#pragma unroll
    for (int i = 0; i < 8; i++) {
        int d = d0 + tyy + 16 * i;
#pragma unroll
        for (int p = 0; p < 2; p++) {
            int k0 = 4 * tx + 2 * p;
            float2 a  = unpack2(acc[i][p]);
            float2 cv = *reinterpret_cast<const float2*>(centers + (size_t)d * KK + k0);
            float2 o  = make_float2(a.x - cv.x * asums[k0],
                                    a.y - cv.y * asums[k0 + 1]);
            *reinterpret_cast<float2*>(g_vlad + ((size_t)b * DD + d) * KK + k0) = o;
        }
    }
}

// ---------------------------------------------------------------------------
// K3: intra-normalize over D per (b,k), then global L2 normalize per b.
// ---------------------------------------------------------------------------
__global__ void __launch_bounds__(256)
k3_normalize(float* __restrict__ out) {
    const int b   = blockIdx.x;
    const int tid = threadIdx.x;
    const int k   = tid & 63;
    const int ds  = tid >> 6;  // 0..3

    const float* vb = g_vlad + (size_t)b * DD * KK;

    float ss = 0.f;
    for (int d = ds; d < DD; d += 4) {
        float v = vb[(size_t)d * KK + k];
        ss = fmaf(v, v, ss);
    }

    __shared__ float red[4][KK];
    __shared__ float invk[KK];
    __shared__ float ginv;

    red[ds][k] = ss;
    __syncthreads();
    if (tid < KK) {
        float t = red[0][tid] + red[1][tid] + red[2][tid] + red[3][tid];
        float nrm = fmaxf(sqrtf(t), 1e-12f);
        float iv = 1.f / nrm;
        invk[tid] = iv;
        red[0][tid] = t * iv * iv;  // contribution to global sum of squares
    }
    __syncthreads();
    if (tid == 0) {
        float g = 0.f;
        for (int i = 0; i < KK; i++) g += red[0][i];
        ginv = 1.f / fmaxf(sqrtf(g), 1e-12f);
    }
    __syncthreads();

    float gi = ginv;
    float* ob = out + (size_t)b * DD * KK;
    for (int d = ds; d < DD; d += 4) {
        ob[(size_t)d * KK + k] = vb[(size_t)d * KK + k] * invk[k] * gi;
    }
}

// ---------------------------------------------------------------------------
extern "C" void kernel_launch(void* const* d_in, const int* in_sizes, int n_in,
                              void* d_out, int out_size) {
    const float* x       = (const float*)d_in[0];  // [32,512,1024]
    const float* conv_w  = (const float*)d_in[1];  // [64,512]
    const float* centers = (const float*)d_in[2];  // [512,64]
    float* out = (float*)d_out;                    // [32, 512*64]

    k1_scores_softmax<<<dim3(NNN / NT1, BB), 256>>>(x, conv_w);
    k2_vlad<<<dim3(DD / 128, BB), 256>>>(x, centers);
    k3_normalize<<<BB, 256>>>(out);
}

// round 2
// speedup vs baseline: 1.0776x; 1.0776x over previous
#include <cuda_runtime.h>

#define BB 32
#define DD 512
#define KK 64
#define NNN 1024

#define NT1 128   // K1 n-tile
#define DT  16    // K1 d-chunk
#define NT2 16    // K2 n-chunk

// Scratch (allocation-free rule: __device__ globals)
__device__ __align__(16) float g_assign[(size_t)BB * KK * NNN];   // 8 MB
__device__ __align__(16) float g_vlad2[2][(size_t)BB * DD * KK];  // 2 x 4 MB

typedef unsigned long long u64;

__device__ __forceinline__ void fma2(u64 &d, u64 a, u64 b) {
    asm("fma.rn.f32x2 %0, %1, %2, %0;" : "+l"(d) : "l"(a), "l"(b));
}
__device__ __forceinline__ float2 unpack2(u64 v) {
    float2 r;
    asm("mov.b64 {%0, %1}, %2;" : "=f"(r.x), "=f"(r.y) : "l"(v));
    return r;
}

// ---------------------------------------------------------------------------
// K1: scores = W @ x  (64k x 128n tile per block), double-buffered smem,
//     fused softmax over K, writes assign[b,k,n].
// Thread: 8 contiguous k (8*tyk..) x 4 contiguous n (4*txn..).
// ---------------------------------------------------------------------------
__global__ void __launch_bounds__(256, 2)
k1_scores_softmax(const float* __restrict__ x, const float* __restrict__ w) {
    // 32 KB: Wdup[2][DT][KK] float2 (16KB) + Xs[2][DT][NT1] float (16KB);
    // softmax overlays the whole thing as Ss[KK][NT1] (32KB).
    __shared__ __align__(16) char smraw[32 * 1024];
    float2 (*Wdup)[DT][KK] = reinterpret_cast<float2(*)[DT][KK]>(smraw);
    float  (*Xs)[DT][NT1]  = reinterpret_cast<float(*)[DT][NT1]>(smraw + 16 * 1024);
    float  (*Ss)[NT1]      = reinterpret_cast<float(*)[NT1]>(smraw);

    const int b   = blockIdx.y;
    const int n0  = blockIdx.x * NT1;
    const int tid = threadIdx.x;
    const int txn = tid & 31;   // n = 4*txn + {0..3}
    const int tyk = tid >> 5;   // k = 8*tyk + {0..7}

    const float* xb = x + (size_t)b * DD * NNN;

    u64 acc[8][2];
#pragma unroll
    for (int i = 0; i < 8; i++) { acc[i][0] = 0ull; acc[i][1] = 0ull; }

    // loader roles
    const int wk   = tid >> 2;         // 0..63
    const int wd4  = (tid & 3) << 2;   // 0,4,8,12
    const int xrow = tid >> 5;         // 0..7
    const int xcol = (tid & 31) << 2;  // 0..124

    float4 wv, xv0, xv1;
    // prologue: chunk 0 -> regs -> buf 0
    wv  = *reinterpret_cast<const float4*>(w  + (size_t)wk * DD + wd4);
    xv0 = *reinterpret_cast<const float4*>(xb + (size_t)xrow * NNN + n0 + xcol);
    xv1 = *reinterpret_cast<const float4*>(xb + (size_t)(xrow + 8) * NNN + n0 + xcol);
    Wdup[0][wd4 + 0][wk] = make_float2(wv.x, wv.x);
    Wdup[0][wd4 + 1][wk] = make_float2(wv.y, wv.y);
    Wdup[0][wd4 + 2][wk] = make_float2(wv.z, wv.z);
    Wdup[0][wd4 + 3][wk] = make_float2(wv.w, wv.w);
    *reinterpret_cast<float4*>(&Xs[0][xrow][xcol])     = xv0;
    *reinterpret_cast<float4*>(&Xs[0][xrow + 8][xcol]) = xv1;
    __syncthreads();

    const int NCHUNK = DD / DT;  // 32
    for (int c = 0; c < NCHUNK; c++) {
        const int cur = c & 1, nxt = cur ^ 1;
        const int dt1 = (c + 1) * DT;
        if (dt1 < DD) {  // prefetch next chunk into registers
            wv  = *reinterpret_cast<const float4*>(w  + (size_t)wk * DD + dt1 + wd4);
            xv0 = *reinterpret_cast<const float4*>(xb + (size_t)(dt1 + xrow) * NNN + n0 + xcol);
            xv1 = *reinterpret_cast<const float4*>(xb + (size_t)(dt1 + xrow + 8) * NNN + n0 + xcol);
        }
#pragma unroll
        for (int dd = 0; dd < DT; dd++) {
            float4 xq = *reinterpret_cast<const float4*>(&Xs[cur][dd][4 * txn]);  // LDS.128, conflict-free
            u64 xp0 = reinterpret_cast<const u64*>(&xq)[0];
            u64 xp1 = reinterpret_cast<const u64*>(&xq)[1];
#pragma unroll
            for (int j = 0; j < 4; j++) {
                float4 wq = *reinterpret_cast<const float4*>(&Wdup[cur][dd][8 * tyk + 2 * j]);  // LDS.128 broadcast
                u64 wp0 = reinterpret_cast<const u64*>(&wq)[0];
                u64 wp1 = reinterpret_cast<const u64*>(&wq)[1];
                fma2(acc[2 * j + 0][0], wp0, xp0);
                fma2(acc[2 * j + 0][1], wp0, xp1);
                fma2(acc[2 * j + 1][0], wp1, xp0);
                fma2(acc[2 * j + 1][1], wp1, xp1);
            }
        }
        if (dt1 < DD) {  // stage prefetched regs into the other buffer
            Wdup[nxt][wd4 + 0][wk] = make_float2(wv.x, wv.x);
            Wdup[nxt][wd4 + 1][wk] = make_float2(wv.y, wv.y);
            Wdup[nxt][wd4 + 2][wk] = make_float2(wv.z, wv.z);
            Wdup[nxt][wd4 + 3][wk] = make_float2(wv.w, wv.w);
            *reinterpret_cast<float4*>(&Xs[nxt][xrow][xcol])     = xv0;
            *reinterpret_cast<float4*>(&Xs[nxt][xrow + 8][xcol]) = xv1;
        }
        __syncthreads();
    }

    // scores -> Ss overlay (safe: loop ended with a sync)
#pragma unroll
    for (int i = 0; i < 8; i++) {
        float2 a0 = unpack2(acc[i][0]);
        float2 a1 = unpack2(acc[i][1]);
        *reinterpret_cast<float4*>(&Ss[8 * tyk + i][4 * txn]) =
            make_float4(a0.x, a0.y, a1.x, a1.y);
    }
    __syncthreads();

    // softmax over K per column
    if (tid < NT1) {
        const int c = tid;
        float mx = -1e30f;
#pragma unroll
        for (int k = 0; k < KK; k++) mx = fmaxf(mx, Ss[k][c]);
        float s = 0.f;
#pragma unroll
        for (int k = 0; k < KK; k++) {
            float e = __expf(Ss[k][c] - mx);
            Ss[k][c] = e;
            s += e;
        }
        float is = 1.f / s;
        float* ab = g_assign + (size_t)b * KK * NNN + n0 + c;
#pragma unroll
        for (int k = 0; k < KK; k++) ab[(size_t)k * NNN] = Ss[k][c] * is;
    }
}

// ---------------------------------------------------------------------------
// K2: partial vlad over an n-half (z = 0/1):
//     g_vlad2[z][b, d0:d0+128, :] = sum_{n in half} x*assign - centers*asum_half
// Thread: 8 contiguous d (8*tyd..) x 4 contiguous k (4*tx..).
// ---------------------------------------------------------------------------
__global__ void __launch_bounds__(256, 2)
k2_vlad(const float* __restrict__ x, const float* __restrict__ centers) {
    __shared__ __align__(16) float2 Xd[2][NT2][128];  // 2 x 16 KB, duplicated pairs
    __shared__ __align__(16) float  As[2][NT2][KK];   // 2 x 4 KB
    __shared__ float asums[KK];

    const int b   = blockIdx.y;
    const int d0  = blockIdx.x * 128;
    const int z   = blockIdx.z;
    const int nb  = z * (NNN / 2);    // 512-wide half
    const int tid = threadIdx.x;
    const int tx  = tid & 15;   // k = 4*tx + {0..3}
    const int tyd = tid >> 4;   // d = d0 + 8*tyd + {0..7}

    const float* xb = x + (size_t)b * DD * NNN;
    const float* ab = g_assign + (size_t)b * KK * NNN;

    u64 acc[8][2];
#pragma unroll
    for (int i = 0; i < 8; i++) { acc[i][0] = 0ull; acc[i][1] = 0ull; }
    float asum = 0.f;

    // loader roles
    const int xd  = tid >> 1;          // 0..127
    const int xnb = (tid & 1) * 8;     // 0 or 8
    const int ak  = tid & 63;          // 0..63
    const int anb = (tid >> 6) * 4;    // 0,4,8,12

    float4 xv0, xv1, av;
    xv0 = *reinterpret_cast<const float4*>(xb + (size_t)(d0 + xd) * NNN + nb + xnb);
    xv1 = *reinterpret_cast<const float4*>(xb + (size_t)(d0 + xd) * NNN + nb + xnb + 4);
    av  = *reinterpret_cast<const float4*>(ab + (size_t)ak * NNN + nb + anb);
    Xd[0][xnb + 0][xd] = make_float2(xv0.x, xv0.x);
    Xd[0][xnb + 1][xd] = make_float2(xv0.y, xv0.y);
    Xd[0][xnb + 2][xd] = make_float2(xv0.z, xv0.z);
    Xd[0][xnb + 3][xd] = make_float2(xv0.w, xv0.w);
    Xd[0][xnb + 4][xd] = make_float2(xv1.x, xv1.x);
    Xd[0][xnb + 5][xd] = make_float2(xv1.y, xv1.y);
    Xd[0][xnb + 6][xd] = make_float2(xv1.z, xv1.z);
    Xd[0][xnb + 7][xd] = make_float2(xv1.w, xv1.w);
    As[0][anb + 0][ak] = av.x;
    As[0][anb + 1][ak] = av.y;
    As[0][anb + 2][ak] = av.z;
    As[0][anb + 3][ak] = av.w;
    __syncthreads();

    const int NCHUNK = (NNN / 2) / NT2;  // 32
    for (int c = 0; c < NCHUNK; c++) {
        const int cur = c & 1, nxt = cur ^ 1;
        const int n1 = nb + (c + 1) * NT2;
        if (c + 1 < NCHUNK) {
            xv0 = *reinterpret_cast<const float4*>(xb + (size_t)(d0 + xd) * NNN + n1 + xnb);
            xv1 = *reinterpret_cast<const float4*>(xb + (size_t)(d0 + xd) * NNN + n1 + xnb + 4);
            av  = *reinterpret_cast<const float4*>(ab + (size_t)ak * NNN + n1 + anb);
        }
        if (tid < KK) {
            float s = 0.f;
#pragma unroll
            for (int nn = 0; nn < NT2; nn++) s += As[cur][nn][tid];
            asum += s;
        }
#pragma unroll
        for (int nn = 0; nn < NT2; nn++) {
            float4 aq = *reinterpret_cast<const float4*>(&As[cur][nn][4 * tx]);  // LDS.128
            u64 ap0 = reinterpret_cast<const u64*>(&aq)[0];
            u64 ap1 = reinterpret_cast<const u64*>(&aq)[1];
#pragma unroll
            for (int i2 = 0; i2 < 4; i2++) {
                float4 xq = *reinterpret_cast<const float4*>(&Xd[cur][nn][8 * tyd + 2 * i2]);  // LDS.128 (2 dup pairs)
                u64 xp0 = reinterpret_cast<const u64*>(&xq)[0];
                u64 xp1 = reinterpret_cast<const u64*>(&xq)[1];
                fma2(acc[2 * i2 + 0][0], xp0, ap0);
                fma2(acc[2 * i2 + 0][1], xp0, ap1);
                fma2(acc[2 * i2 + 1][0], xp1, ap0);
                fma2(acc[2 * i2 + 1][1], xp1, ap1);
            }
        }
        if (c + 1 < NCHUNK) {
            Xd[nxt][xnb + 0][xd] = make_float2(xv0.x, xv0.x);
            Xd[nxt][xnb + 1][xd] = make_float2(xv0.y, xv0.y);
            Xd[nxt][xnb + 2][xd] = make_float2(xv0.z, xv0.z);
            Xd[nxt][xnb + 3][xd] = make_float2(xv0.w, xv0.w);
            Xd[nxt][xnb + 4][xd] = make_float2(xv1.x, xv1.x);
            Xd[nxt][xnb + 5][xd] = make_float2(xv1.y, xv1.y);
            Xd[nxt][xnb + 6][xd] = make_float2(xv1.z, xv1.z);
            Xd[nxt][xnb + 7][xd] = make_float2(xv1.w, xv1.w);
            As[nxt][anb + 0][ak] = av.x;
            As[nxt][anb + 1][ak] = av.y;
            As[nxt][anb + 2][ak] = av.z;
            As[nxt][anb + 3][ak] = av.w;
        }
        __syncthreads();
    }

    if (tid < KK) asums[tid] = asum;   // partial asum for this half
    __syncthreads();

    // epilogue: subtract centers * asum_half (linear, halves sum correctly)
    float* vz = g_vlad2[z];
#pragma unroll
    for (int i = 0; i < 8; i++) {
        int d = d0 + 8 * tyd + i;
#pragma unroll
        for (int p = 0; p < 2; p++) {
            int k0 = 4 * tx + 2 * p;
            float2 a  = unpack2(acc[i][p]);
            float2 cv = *reinterpret_cast<const float2*>(centers + (size_t)d * KK + k0);
            float2 o  = make_float2(a.x - cv.x * asums[k0],
                                    a.y - cv.y * asums[k0 + 1]);
            *reinterpret_cast<float2*>(vz + ((size_t)b * DD + d) * KK + k0) = o;
        }
    }
}

// ---------------------------------------------------------------------------
// K3: combine halves, intra-normalize over D per (b,k), global L2 normalize.
// ---------------------------------------------------------------------------
__global__ void __launch_bounds__(256)
k3_normalize(float* __restrict__ out) {
    const int b   = blockIdx.x;
    const int tid = threadIdx.x;
    const int k   = tid & 63;
    const int ds  = tid >> 6;  // 0..3

    const float* v0 = g_vlad2[0] + (size_t)b * DD * KK;
    const float* v1 = g_vlad2[1] + (size_t)b * DD * KK;

    float ss = 0.f;
    for (int d = ds; d < DD; d += 4) {
        float v = v0[(size_t)d * KK + k] + v1[(size_t)d * KK + k];
        ss = fmaf(v, v, ss);
    }

    __shared__ float red[4][KK];
    __shared__ float invk[KK];
    __shared__ float ginv;

    red[ds][k] = ss;
    __syncthreads();
    if (tid < KK) {
        float t = red[0][tid] + red[1][tid] + red[2][tid] + red[3][tid];
        float nrm = fmaxf(sqrtf(t), 1e-12f);
        float iv = 1.f / nrm;
        invk[tid] = iv;
        red[0][tid] = t * iv * iv;
    }
    __syncthreads();
    if (tid == 0) {
        float g = 0.f;
        for (int i = 0; i < KK; i++) g += red[0][i];
        ginv = 1.f / fmaxf(sqrtf(g), 1e-12f);
    }
    __syncthreads();

    const float gi = ginv;
    float* ob = out + (size_t)b * DD * KK;
    for (int d = ds; d < DD; d += 4) {
        float v = v0[(size_t)d * KK + k] + v1[(size_t)d * KK + k];
        ob[(size_t)d * KK + k] = v * invk[k] * gi;
    }
}

// ---------------------------------------------------------------------------
extern "C" void kernel_launch(void* const* d_in, const int* in_sizes, int n_in,
                              void* d_out, int out_size) {
    const float* x       = (const float*)d_in[0];  // [32,512,1024]
    const float* conv_w  = (const float*)d_in[1];  // [64,512]
    const float* centers = (const float*)d_in[2];  // [512,64]
    float* out = (float*)d_out;                    // [32, 512*64]

    k1_scores_softmax<<<dim3(NNN / NT1, BB), 256>>>(x, conv_w);
    k2_vlad<<<dim3(DD / 128, BB, 2), 256>>>(x, centers);
    k3_normalize<<<BB, 256>>>(out);
}